// round 6
// baseline (speedup 1.0000x reference)
#include <cuda_runtime.h>
#include <cuda_bf16.h>

#define N_NODES 50000
#define E_EDGES 800000
#define D 64
#define NC 40
#define RB 128            // rows per block in GEMM kernels
#define NPB 16            // nodes per block in aggregation

// Scratch (allocation-free rule: __device__ globals). 16B-aligned for float4 access.
__device__ __align__(16) float g_dinv[N_NODES];
__device__ __align__(16) float g_hs [N_NODES * D];   // pre-scaled transformed features
__device__ __align__(16) float g_agg[N_NODES * D];   // aggregation result
__device__ int g_cnt   [N_NODES];                    // in-degree (excl self)
__device__ int g_rowptr[N_NODES + 1];                // CSR row pointers
__device__ int g_cursor[N_NODES];                    // fill cursors
__device__ int g_eid   [E_EDGES];                    // CSR column indices (src ids)

// ---------------------------------------------------------------------------
// CSR build: count -> scan (+dinv) -> fill
// ---------------------------------------------------------------------------
__global__ void k_zero_cnt() {
    int i = blockIdx.x * blockDim.x + threadIdx.x;
    if (i < N_NODES) g_cnt[i] = 0;
}

__global__ void k_count(const int* __restrict__ dst) {
    int e = blockIdx.x * blockDim.x + threadIdx.x;
    if (e < E_EDGES) atomicAdd(&g_cnt[dst[e]], 1);
}

// Single-block exclusive scan over 50k ints; also writes rowptr, cursor, dinv.
__global__ void k_scan() {
    __shared__ int s[1024];
    const int PER = (N_NODES + 1023) / 1024;   // 49
    int t = threadIdx.x;
    int base = t * PER;
    int sum = 0;
    #pragma unroll 4
    for (int i = 0; i < PER; i++) {
        int idx = base + i;
        if (idx < N_NODES) sum += g_cnt[idx];
    }
    s[t] = sum;
    __syncthreads();
    for (int off = 1; off < 1024; off <<= 1) {
        int v = (t >= off) ? s[t - off] : 0;
        __syncthreads();
        s[t] += v;
        __syncthreads();
    }
    int run = s[t] - sum;   // exclusive prefix of this thread's chunk
    #pragma unroll 4
    for (int i = 0; i < PER; i++) {
        int idx = base + i;
        if (idx < N_NODES) {
            g_rowptr[idx] = run;
            g_cursor[idx] = run;
            int c = g_cnt[idx];
            g_dinv[idx] = rsqrtf((float)(c + 1));   // +1 self-loop
            run += c;
        }
    }
    if (t == 0) g_rowptr[N_NODES] = E_EDGES;
}

__global__ void k_fill(const int* __restrict__ src, const int* __restrict__ dst) {
    int e = blockIdx.x * blockDim.x + threadIdx.x;
    if (e < E_EDGES) {
        int d = dst[e];
        int p = atomicAdd(&g_cursor[d], 1);
        g_eid[p] = src[e];
    }
}

// ---------------------------------------------------------------------------
// Layer-1 GEMM: hs = (x @ W1) * dinv[row]
// 128 rows/block, 256 threads, 8x4 register tile per thread.
// ---------------------------------------------------------------------------
__global__ void k_gemm1(const float* __restrict__ x, const float* __restrict__ W1) {
    __shared__ float sW[D][D];       // 16 KB
    __shared__ float sx[RB][D];      // 32 KB
    int tid = threadIdx.x;
    int row0 = blockIdx.x * RB;

    #pragma unroll
    for (int i = 0; i < 4; i++) {
        int idx = tid * 4 + i * 1024;
        *reinterpret_cast<float4*>(&sW[0][0] + idx) =
            *reinterpret_cast<const float4*>(W1 + idx);
    }
    #pragma unroll
    for (int i = 0; i < 8; i++) {
        int lin = tid + i * 256;             // float4-unit index
        int r = lin >> 4;
        int c4 = (lin & 15) * 4;
        int row = row0 + r;
        float4 v = make_float4(0.f, 0.f, 0.f, 0.f);
        if (row < N_NODES) v = *reinterpret_cast<const float4*>(x + (size_t)row * D + c4);
        *reinterpret_cast<float4*>(&sx[r][c4]) = v;
    }
    __syncthreads();

    int tc = tid & 15;           // cols tc*4 .. +3
    int tr = tid >> 4;           // rows tr*8 .. +7
    float4 acc[8];
    #pragma unroll
    for (int i = 0; i < 8; i++) acc[i] = make_float4(0.f, 0.f, 0.f, 0.f);
    #pragma unroll
    for (int k = 0; k < D; k++) {
        float4 w = *reinterpret_cast<float4*>(&sW[k][tc * 4]);
        #pragma unroll
        for (int i = 0; i < 8; i++) {
            float xv = sx[tr * 8 + i][k];
            acc[i].x = fmaf(xv, w.x, acc[i].x);
            acc[i].y = fmaf(xv, w.y, acc[i].y);
            acc[i].z = fmaf(xv, w.z, acc[i].z);
            acc[i].w = fmaf(xv, w.w, acc[i].w);
        }
    }
    #pragma unroll
    for (int i = 0; i < 8; i++) {
        int row = row0 + tr * 8 + i;
        if (row < N_NODES) {
            float di = g_dinv[row];
            float4 v = make_float4(acc[i].x * di, acc[i].y * di, acc[i].z * di, acc[i].w * di);
            *reinterpret_cast<float4*>(g_hs + (size_t)row * D + tc * 4) = v;
        }
    }
}

// ---------------------------------------------------------------------------
// CSR gather aggregation: agg[n] = hs[n] + sum_{s in inNbr(n)} hs[s]
// 16 lanes per node, register accumulation, single write.
// ---------------------------------------------------------------------------
__global__ void k_agg() {
    int tid = threadIdx.x;
    int node = blockIdx.x * NPB + (tid >> 4);
    int lane = tid & 15;
    if (node >= N_NODES) return;
    const float4* hs4 = reinterpret_cast<const float4*>(g_hs);
    float4 acc = hs4[(size_t)node * 16 + lane];       // self-loop term
    int j   = g_rowptr[node];
    int end = g_rowptr[node + 1];
    for (; j + 1 < end; j += 2) {
        int s0 = g_eid[j];
        int s1 = g_eid[j + 1];
        float4 a = hs4[(size_t)s0 * 16 + lane];
        float4 b = hs4[(size_t)s1 * 16 + lane];
        acc.x += a.x; acc.y += a.y; acc.z += a.z; acc.w += a.w;
        acc.x += b.x; acc.y += b.y; acc.z += b.z; acc.w += b.w;
    }
    if (j < end) {
        int s0 = g_eid[j];
        float4 a = hs4[(size_t)s0 * 16 + lane];
        acc.x += a.x; acc.y += a.y; acc.z += a.z; acc.w += a.w;
    }
    reinterpret_cast<float4*>(g_agg)[(size_t)node * 16 + lane] = acc;
}

// ---------------------------------------------------------------------------
// Fused: h1 = tanh(agg * dinv + b1); hs = (h1 @ W2) * dinv
// ---------------------------------------------------------------------------
__global__ void k_layer2(const float* __restrict__ W2, const float* __restrict__ b1) {
    __shared__ float sW[D][D];
    __shared__ float st[RB][D];
    int tid = threadIdx.x;
    int row0 = blockIdx.x * RB;

    #pragma unroll
    for (int i = 0; i < 4; i++) {
        int idx = tid * 4 + i * 1024;
        *reinterpret_cast<float4*>(&sW[0][0] + idx) =
            *reinterpret_cast<const float4*>(W2 + idx);
    }
    #pragma unroll
    for (int i = 0; i < 8; i++) {
        int lin = tid + i * 256;
        int r = lin >> 4;
        int c4 = (lin & 15) * 4;
        int row = row0 + r;
        float4 v = make_float4(0.f, 0.f, 0.f, 0.f);
        if (row < N_NODES) {
            float di = g_dinv[row];
            float4 a = *reinterpret_cast<const float4*>(g_agg + (size_t)row * D + c4);
            float4 b = *reinterpret_cast<const float4*>(b1 + c4);   // L1-cached
            v.x = tanhf(fmaf(a.x, di, b.x));
            v.y = tanhf(fmaf(a.y, di, b.y));
            v.z = tanhf(fmaf(a.z, di, b.z));
            v.w = tanhf(fmaf(a.w, di, b.w));
        }
        *reinterpret_cast<float4*>(&st[r][c4]) = v;
    }
    __syncthreads();

    int tc = tid & 15;
    int tr = tid >> 4;
    float4 acc[8];
    #pragma unroll
    for (int i = 0; i < 8; i++) acc[i] = make_float4(0.f, 0.f, 0.f, 0.f);
    #pragma unroll
    for (int k = 0; k < D; k++) {
        float4 w = *reinterpret_cast<float4*>(&sW[k][tc * 4]);
        #pragma unroll
        for (int i = 0; i < 8; i++) {
            float xv = st[tr * 8 + i][k];
            acc[i].x = fmaf(xv, w.x, acc[i].x);
            acc[i].y = fmaf(xv, w.y, acc[i].y);
            acc[i].z = fmaf(xv, w.z, acc[i].z);
            acc[i].w = fmaf(xv, w.w, acc[i].w);
        }
    }
    #pragma unroll
    for (int i = 0; i < 8; i++) {
        int row = row0 + tr * 8 + i;
        if (row < N_NODES) {
            float di = g_dinv[row];
            float4 v = make_float4(acc[i].x * di, acc[i].y * di, acc[i].z * di, acc[i].w * di);
            *reinterpret_cast<float4*>(g_hs + (size_t)row * D + tc * 4) = v;
        }
    }
}

// ---------------------------------------------------------------------------
// Fused final: h = tanh(agg * dinv + b2)  -> d_out[N*NC ..]  (h output)
//              out = h @ Wc + bc          -> d_out[0 .. N*NC) (logits)
// ---------------------------------------------------------------------------
__global__ void k_final(const float* __restrict__ Wc, const float* __restrict__ b2,
                        const float* __restrict__ bc, float* __restrict__ out) {
    __shared__ float sW[D][NC];      // 10.2 KB
    __shared__ float st[RB][D];      // 32 KB
    int tid = threadIdx.x;
    int row0 = blockIdx.x * RB;

    #pragma unroll
    for (int i = 0; i < 3; i++) {
        int f4 = tid + i * 256;
        if (f4 < D * NC / 4)
            *(reinterpret_cast<float4*>(&sW[0][0]) + f4) =
                *(reinterpret_cast<const float4*>(Wc) + f4);
    }
    #pragma unroll
    for (int i = 0; i < 8; i++) {
        int lin = tid + i * 256;
        int r = lin >> 4;
        int c4 = (lin & 15) * 4;
        int row = row0 + r;
        float4 v = make_float4(0.f, 0.f, 0.f, 0.f);
        if (row < N_NODES) {
            float di = g_dinv[row];
            float4 a = *reinterpret_cast<const float4*>(g_agg + (size_t)row * D + c4);
            float4 b = *reinterpret_cast<const float4*>(b2 + c4);
            v.x = tanhf(fmaf(a.x, di, b.x));
            v.y = tanhf(fmaf(a.y, di, b.y));
            v.z = tanhf(fmaf(a.z, di, b.z));
            v.w = tanhf(fmaf(a.w, di, b.w));
            *reinterpret_cast<float4*>(out + (size_t)N_NODES * NC + (size_t)row * D + c4) = v;
        }
        *reinterpret_cast<float4*>(&st[r][c4]) = v;
    }
    __syncthreads();

    int tc = tid & 15;
    int tr = tid >> 4;
    if (tc < NC / 4) {
        float4 bcv = *reinterpret_cast<const float4*>(bc + tc * 4);
        float4 acc[8];
        #pragma unroll
        for (int i = 0; i < 8; i++) acc[i] = bcv;
        #pragma unroll
        for (int k = 0; k < D; k++) {
            float4 w = *reinterpret_cast<float4*>(&sW[k][tc * 4]);
            #pragma unroll
            for (int i = 0; i < 8; i++) {
                float xv = st[tr * 8 + i][k];
                acc[i].x = fmaf(xv, w.x, acc[i].x);
                acc[i].y = fmaf(xv, w.y, acc[i].y);
                acc[i].z = fmaf(xv, w.z, acc[i].z);
                acc[i].w = fmaf(xv, w.w, acc[i].w);
            }
        }
        #pragma unroll
        for (int i = 0; i < 8; i++) {
            int row = row0 + tr * 8 + i;
            if (row < N_NODES)
                *reinterpret_cast<float4*>(out + (size_t)row * NC + tc * 4) = acc[i];
        }
    }
}

// ---------------------------------------------------------------------------
extern "C" void kernel_launch(void* const* d_in, const int* in_sizes, int n_in,
                              void* d_out, int out_size) {
    const float* x   = (const float*)d_in[0];
    const int*   ei  = (const int*)d_in[1];   // [2, E] int32 (JAX x64 disabled)
    const float* W1  = (const float*)d_in[2];
    const float* b1  = (const float*)d_in[3];
    const float* W2  = (const float*)d_in[4];
    const float* b2  = (const float*)d_in[5];
    const float* Wc  = (const float*)d_in[6];
    const float* bc  = (const float*)d_in[7];
    float* out = (float*)d_out;

    const int* src = ei;              // edge_index[0]
    const int* dst = ei + E_EDGES;    // edge_index[1]

    const int TB = 256;
    const int gN    = (N_NODES + TB - 1) / TB;
    const int gE    = (E_EDGES + TB - 1) / TB;
    const int gRows = (N_NODES + RB - 1) / RB;            // 391
    const int gAgg  = (N_NODES + NPB - 1) / NPB;          // 3125

    // CSR build + dinv
    k_zero_cnt<<<gN, TB>>>();
    k_count   <<<gE, TB>>>(dst);
    k_scan    <<<1, 1024>>>();
    k_fill    <<<gE, TB>>>(src, dst);

    // Layer pipeline
    k_gemm1  <<<gRows, TB>>>(x, W1);
    k_agg    <<<gAgg, TB>>>();
    k_layer2 <<<gRows, TB>>>(W2, b1);
    k_agg    <<<gAgg, TB>>>();
    k_final  <<<gRows, TB>>>(Wc, b2, bc, out);
}

// round 7
// speedup vs baseline: 1.4683x; 1.4683x over previous
#include <cuda_runtime.h>
#include <cuda_bf16.h>

#define N_NODES 50000
#define E_EDGES 800000
#define D 64
#define NC 40
#define RB 128            // rows per block in GEMM kernels

// Scratch (allocation-free rule: __device__ globals). 16B-aligned for float4 access.
__device__ __align__(16) float g_dinv[N_NODES];      // deg, then rsqrt(deg) in place
__device__ __align__(16) float g_hs [N_NODES * D];   // pre-scaled transformed features
__device__ __align__(16) float g_agg[N_NODES * D];   // aggregation target

// ---------------------------------------------------------------------------
// Degree: deg[i] = 1 (self-loop) + #edges with dst==i ; then dinv = rsqrt(deg)
// ---------------------------------------------------------------------------
__global__ void k_init_deg() {
    int i = blockIdx.x * blockDim.x + threadIdx.x;
    if (i < N_NODES) g_dinv[i] = 1.0f;
}

__global__ void k_count_deg(const int* __restrict__ dst) {
    int e = blockIdx.x * blockDim.x + threadIdx.x;
    if (e < E_EDGES) atomicAdd(&g_dinv[dst[e]], 1.0f);
}

__global__ void k_finish_dinv() {
    int i = blockIdx.x * blockDim.x + threadIdx.x;
    if (i < N_NODES) g_dinv[i] = rsqrtf(g_dinv[i]);
}

// ---------------------------------------------------------------------------
// Layer-1 GEMM: hs = (x @ W1) * dinv[row]; agg = hs (self-loop term)
// 128 rows/block, 256 threads, 8x4 register tile per thread.
// ---------------------------------------------------------------------------
__global__ void k_gemm1(const float* __restrict__ x, const float* __restrict__ W1) {
    __shared__ float sW[D][D];       // 16 KB
    __shared__ float sx[RB][D];      // 32 KB
    int tid = threadIdx.x;
    int row0 = blockIdx.x * RB;

    #pragma unroll
    for (int i = 0; i < 4; i++) {
        int idx = tid * 4 + i * 1024;
        *reinterpret_cast<float4*>(&sW[0][0] + idx) =
            *reinterpret_cast<const float4*>(W1 + idx);
    }
    #pragma unroll
    for (int i = 0; i < 8; i++) {
        int lin = tid + i * 256;             // float4-unit index
        int r = lin >> 4;
        int c4 = (lin & 15) * 4;
        int row = row0 + r;
        float4 v = make_float4(0.f, 0.f, 0.f, 0.f);
        if (row < N_NODES) v = *reinterpret_cast<const float4*>(x + (size_t)row * D + c4);
        *reinterpret_cast<float4*>(&sx[r][c4]) = v;
    }
    __syncthreads();

    int tc = tid & 15;           // cols tc*4 .. +3
    int tr = tid >> 4;           // rows tr*8 .. +7
    float4 acc[8];
    #pragma unroll
    for (int i = 0; i < 8; i++) acc[i] = make_float4(0.f, 0.f, 0.f, 0.f);
    #pragma unroll
    for (int k = 0; k < D; k++) {
        float4 w = *reinterpret_cast<float4*>(&sW[k][tc * 4]);
        #pragma unroll
        for (int i = 0; i < 8; i++) {
            float xv = sx[tr * 8 + i][k];
            acc[i].x = fmaf(xv, w.x, acc[i].x);
            acc[i].y = fmaf(xv, w.y, acc[i].y);
            acc[i].z = fmaf(xv, w.z, acc[i].z);
            acc[i].w = fmaf(xv, w.w, acc[i].w);
        }
    }
    #pragma unroll
    for (int i = 0; i < 8; i++) {
        int row = row0 + tr * 8 + i;
        if (row < N_NODES) {
            float di = g_dinv[row];
            float4 v = make_float4(acc[i].x * di, acc[i].y * di, acc[i].z * di, acc[i].w * di);
            *reinterpret_cast<float4*>(g_hs  + (size_t)row * D + tc * 4) = v;
            *reinterpret_cast<float4*>(g_agg + (size_t)row * D + tc * 4) = v;
        }
    }
}

// ---------------------------------------------------------------------------
// Edge scatter: agg[dst] += hs[src]. 16 threads/edge, one float4 gather +
// one 128-bit vector reduction (sm_90+ atomicAdd(float4*)).
// ---------------------------------------------------------------------------
__global__ void k_scatter(const int* __restrict__ src,
                          const int* __restrict__ dst) {
    long long idx = (long long)blockIdx.x * blockDim.x + threadIdx.x;
    int e = (int)(idx >> 4);
    int c = (int)(idx & 15);
    if (e >= E_EDGES) return;
    int s = src[e];
    int d = dst[e];
    float4 v = reinterpret_cast<const float4*>(g_hs + (size_t)s * D)[c];
    atomicAdd(reinterpret_cast<float4*>(g_agg + (size_t)d * D) + c, v);
}

// ---------------------------------------------------------------------------
// Fused: h1 = tanh(agg * dinv + b1); hs = (h1 @ W2) * dinv; agg = hs
// ---------------------------------------------------------------------------
__global__ void k_layer2(const float* __restrict__ W2, const float* __restrict__ b1) {
    __shared__ float sW[D][D];
    __shared__ float st[RB][D];
    int tid = threadIdx.x;
    int row0 = blockIdx.x * RB;

    #pragma unroll
    for (int i = 0; i < 4; i++) {
        int idx = tid * 4 + i * 1024;
        *reinterpret_cast<float4*>(&sW[0][0] + idx) =
            *reinterpret_cast<const float4*>(W2 + idx);
    }
    #pragma unroll
    for (int i = 0; i < 8; i++) {
        int lin = tid + i * 256;
        int r = lin >> 4;
        int c4 = (lin & 15) * 4;
        int row = row0 + r;
        float4 v = make_float4(0.f, 0.f, 0.f, 0.f);
        if (row < N_NODES) {
            float di = g_dinv[row];
            float4 a = *reinterpret_cast<const float4*>(g_agg + (size_t)row * D + c4);
            float4 b = *reinterpret_cast<const float4*>(b1 + c4);   // L1-cached
            v.x = tanhf(fmaf(a.x, di, b.x));
            v.y = tanhf(fmaf(a.y, di, b.y));
            v.z = tanhf(fmaf(a.z, di, b.z));
            v.w = tanhf(fmaf(a.w, di, b.w));
        }
        *reinterpret_cast<float4*>(&st[r][c4]) = v;
    }
    __syncthreads();

    int tc = tid & 15;
    int tr = tid >> 4;
    float4 acc[8];
    #pragma unroll
    for (int i = 0; i < 8; i++) acc[i] = make_float4(0.f, 0.f, 0.f, 0.f);
    #pragma unroll
    for (int k = 0; k < D; k++) {
        float4 w = *reinterpret_cast<float4*>(&sW[k][tc * 4]);
        #pragma unroll
        for (int i = 0; i < 8; i++) {
            float xv = st[tr * 8 + i][k];
            acc[i].x = fmaf(xv, w.x, acc[i].x);
            acc[i].y = fmaf(xv, w.y, acc[i].y);
            acc[i].z = fmaf(xv, w.z, acc[i].z);
            acc[i].w = fmaf(xv, w.w, acc[i].w);
        }
    }
    #pragma unroll
    for (int i = 0; i < 8; i++) {
        int row = row0 + tr * 8 + i;
        if (row < N_NODES) {
            float di = g_dinv[row];
            float4 v = make_float4(acc[i].x * di, acc[i].y * di, acc[i].z * di, acc[i].w * di);
            *reinterpret_cast<float4*>(g_hs  + (size_t)row * D + tc * 4) = v;
            *reinterpret_cast<float4*>(g_agg + (size_t)row * D + tc * 4) = v;
        }
    }
}

// ---------------------------------------------------------------------------
// Fused final: h = tanh(agg * dinv + b2)  -> d_out[N*NC ..]  (h output)
//              out = h @ Wc + bc          -> d_out[0 .. N*NC) (logits)
// ---------------------------------------------------------------------------
__global__ void k_final(const float* __restrict__ Wc, const float* __restrict__ b2,
                        const float* __restrict__ bc, float* __restrict__ out) {
    __shared__ float sW[D][NC];      // 10.2 KB
    __shared__ float st[RB][D];      // 32 KB
    int tid = threadIdx.x;
    int row0 = blockIdx.x * RB;

    #pragma unroll
    for (int i = 0; i < 3; i++) {
        int f4 = tid + i * 256;
        if (f4 < D * NC / 4)
            *(reinterpret_cast<float4*>(&sW[0][0]) + f4) =
                *(reinterpret_cast<const float4*>(Wc) + f4);
    }
    #pragma unroll
    for (int i = 0; i < 8; i++) {
        int lin = tid + i * 256;
        int r = lin >> 4;
        int c4 = (lin & 15) * 4;
        int row = row0 + r;
        float4 v = make_float4(0.f, 0.f, 0.f, 0.f);
        if (row < N_NODES) {
            float di = g_dinv[row];
            float4 a = *reinterpret_cast<const float4*>(g_agg + (size_t)row * D + c4);
            float4 b = *reinterpret_cast<const float4*>(b2 + c4);
            v.x = tanhf(fmaf(a.x, di, b.x));
            v.y = tanhf(fmaf(a.y, di, b.y));
            v.z = tanhf(fmaf(a.z, di, b.z));
            v.w = tanhf(fmaf(a.w, di, b.w));
            *reinterpret_cast<float4*>(out + (size_t)N_NODES * NC + (size_t)row * D + c4) = v;
        }
        *reinterpret_cast<float4*>(&st[r][c4]) = v;
    }
    __syncthreads();

    int tc = tid & 15;
    int tr = tid >> 4;
    if (tc < NC / 4) {
        float4 bcv = *reinterpret_cast<const float4*>(bc + tc * 4);
        float4 acc[8];
        #pragma unroll
        for (int i = 0; i < 8; i++) acc[i] = bcv;
        #pragma unroll
        for (int k = 0; k < D; k++) {
            float4 w = *reinterpret_cast<float4*>(&sW[k][tc * 4]);
            #pragma unroll
            for (int i = 0; i < 8; i++) {
                float xv = st[tr * 8 + i][k];
                acc[i].x = fmaf(xv, w.x, acc[i].x);
                acc[i].y = fmaf(xv, w.y, acc[i].y);
                acc[i].z = fmaf(xv, w.z, acc[i].z);
                acc[i].w = fmaf(xv, w.w, acc[i].w);
            }
        }
        #pragma unroll
        for (int i = 0; i < 8; i++) {
            int row = row0 + tr * 8 + i;
            if (row < N_NODES)
                *reinterpret_cast<float4*>(out + (size_t)row * NC + tc * 4) = acc[i];
        }
    }
}

// ---------------------------------------------------------------------------
extern "C" void kernel_launch(void* const* d_in, const int* in_sizes, int n_in,
                              void* d_out, int out_size) {
    const float* x   = (const float*)d_in[0];
    const int*   ei  = (const int*)d_in[1];   // [2, E] int32 (JAX x64 disabled)
    const float* W1  = (const float*)d_in[2];
    const float* b1  = (const float*)d_in[3];
    const float* W2  = (const float*)d_in[4];
    const float* b2  = (const float*)d_in[5];
    const float* Wc  = (const float*)d_in[6];
    const float* bc  = (const float*)d_in[7];
    float* out = (float*)d_out;

    const int* src = ei;              // edge_index[0]
    const int* dst = ei + E_EDGES;    // edge_index[1]

    const int TB = 256;
    const int gN    = (N_NODES + TB - 1) / TB;
    const int gE    = (E_EDGES + TB - 1) / TB;
    const int gRows = (N_NODES + RB - 1) / RB;            // 391
    const long long scatterThreads = (long long)E_EDGES * 16;
    const int gScat = (int)((scatterThreads + TB - 1) / TB);

    k_init_deg   <<<gN, TB>>>();
    k_count_deg  <<<gE, TB>>>(dst);
    k_finish_dinv<<<gN, TB>>>();

    k_gemm1   <<<gRows, TB>>>(x, W1);
    k_scatter <<<gScat, TB>>>(src, dst);
    k_layer2  <<<gRows, TB>>>(W2, b1);
    k_scatter <<<gScat, TB>>>(src, dst);
    k_final   <<<gRows, TB>>>(Wc, b2, bc, out);
}